// round 1
// baseline (speedup 1.0000x reference)
#include <cuda_runtime.h>
#include <cuda_fp16.h>

// Problem: SelfAttention  B=8, S=2048, D=512, fp32 in/out.
// Inputs in metadata order: d_in[0]=value, d_in[1]=key, d_in[2]=query.
//
// Kernel 1: convert fp32 -> fp16 scratch (Q pre-scaled by 1/sqrt(D)).
// Kernel 2: fused flash attention, one CTA per (batch, 64-query tile),
//           512 threads, mma.sync m16n8k16 f32.f16 for QK^T and P@V,
//           online softmax, fp32 accumulators.

#define BB 8
#define SS 2048
#define DD 512
#define BM 64
#define BN 64
#define NTHREADS 512
#define STRIDE 520              // halves per smem tile row (pad: conflict-free LDSM)

// ---- smem layout (bytes) ----
#define OFF_K 66560             // 64*520*2
#define OFF_V 133120
#define OFF_S 199680
#define OFF_M 216064
#define OFF_L 216320
#define OFF_F 216576
#define SMEM_BYTES 216832
#define PSTRIDE 72              // halves per P row (overlaid on sS)

__device__ __half g_Qh[BB * SS * DD];
__device__ __half g_Kh[BB * SS * DD];
__device__ __half g_Vh[BB * SS * DD];

// ---------------------------------------------------------------------------
__global__ void convert_all_kernel(const float* __restrict__ v,
                                   const float* __restrict__ k,
                                   const float* __restrict__ q) {
    const float qscale = 0.044194173824159216f;  // 1/sqrt(512)
    const int n4 = BB * SS * DD / 4;
    for (int i = blockIdx.x * blockDim.x + threadIdx.x; i < n4;
         i += gridDim.x * blockDim.x) {
        float4 a = ((const float4*)q)[i];
        ((__half2*)g_Qh)[2 * i]     = __floats2half2_rn(a.x * qscale, a.y * qscale);
        ((__half2*)g_Qh)[2 * i + 1] = __floats2half2_rn(a.z * qscale, a.w * qscale);
        float4 bk = ((const float4*)k)[i];
        ((__half2*)g_Kh)[2 * i]     = __floats2half2_rn(bk.x, bk.y);
        ((__half2*)g_Kh)[2 * i + 1] = __floats2half2_rn(bk.z, bk.w);
        float4 c = ((const float4*)v)[i];
        ((__half2*)g_Vh)[2 * i]     = __floats2half2_rn(c.x, c.y);
        ((__half2*)g_Vh)[2 * i + 1] = __floats2half2_rn(c.z, c.w);
    }
}

// ---------------------------------------------------------------------------
__device__ __forceinline__ void ldsm_x4(unsigned& r0, unsigned& r1, unsigned& r2,
                                        unsigned& r3, unsigned addr) {
    asm volatile("ldmatrix.sync.aligned.m8n8.x4.shared.b16 {%0,%1,%2,%3}, [%4];"
                 : "=r"(r0), "=r"(r1), "=r"(r2), "=r"(r3)
                 : "r"(addr));
}
__device__ __forceinline__ void ldsm_x2_trans(unsigned& r0, unsigned& r1,
                                              unsigned addr) {
    asm volatile("ldmatrix.sync.aligned.m8n8.x2.trans.shared.b16 {%0,%1}, [%2];"
                 : "=r"(r0), "=r"(r1)
                 : "r"(addr));
}
__device__ __forceinline__ void mma16816(float* d, unsigned a0, unsigned a1,
                                         unsigned a2, unsigned a3, unsigned b0,
                                         unsigned b1) {
    asm volatile(
        "mma.sync.aligned.m16n8k16.row.col.f32.f16.f16.f32 "
        "{%0,%1,%2,%3}, {%4,%5,%6,%7}, {%8,%9}, {%0,%1,%2,%3};"
        : "+f"(d[0]), "+f"(d[1]), "+f"(d[2]), "+f"(d[3])
        : "r"(a0), "r"(a1), "r"(a2), "r"(a3), "r"(b0), "r"(b1));
}

// ---------------------------------------------------------------------------
__global__ void __launch_bounds__(NTHREADS, 1)
attn_kernel(float* __restrict__ out) {
    extern __shared__ char smem[];
    __half* sQ = (__half*)(smem);
    __half* sK = (__half*)(smem + OFF_K);
    __half* sV = (__half*)(smem + OFF_V);
    float*  sS = (float*)(smem + OFF_S);
    __half* sP = (__half*)(smem + OFF_S);   // overlaid; guarded by barriers
    float*  sM = (float*)(smem + OFF_M);
    float*  sL = (float*)(smem + OFF_L);
    float*  sF = (float*)(smem + OFF_F);

    const int tid  = threadIdx.x;
    const int warp = tid >> 5;
    const int lane = tid & 31;
    const int b    = blockIdx.y;
    const int q0   = blockIdx.x * BM;

    const __half* Qg = g_Qh + ((size_t)b * SS + q0) * DD;
    const __half* Kg = g_Kh + (size_t)b * SS * DD;
    const __half* Vg = g_Vh + (size_t)b * SS * DD;

    // ---- load Q tile (64 x 512 halves) ----
    #pragma unroll
    for (int i = tid; i < BM * 64; i += NTHREADS) {
        int r = i >> 6, c = i & 63;
        *(int4*)(sQ + r * STRIDE + c * 8) = *(const int4*)(Qg + r * DD + c * 8);
    }
    if (tid < BM) { sM[tid] = -1e30f; sL[tid] = 0.f; }

    // warp roles: QK 4x4 (16x16 S each); PV 2x8 (32 rows x 64 cols each)
    const int qwm = warp >> 2, qwn = warp & 3;
    const int wm  = warp >> 3, wn  = warp & 7;

    float acc[2][8][4];
    #pragma unroll
    for (int m = 0; m < 2; m++)
        #pragma unroll
        for (int n = 0; n < 8; n++)
            #pragma unroll
            for (int d = 0; d < 4; d++) acc[m][n][d] = 0.f;

    const unsigned sQa = (unsigned)__cvta_generic_to_shared(sQ);
    const unsigned sKa = (unsigned)__cvta_generic_to_shared(sK);
    const unsigned sVa = (unsigned)__cvta_generic_to_shared(sV);
    const unsigned sPa = (unsigned)__cvta_generic_to_shared(sP);

    const unsigned aQ = sQa + (((qwm * 16 + (lane & 15)) * STRIDE + (lane >> 4) * 8) << 1);
    const unsigned bK = sKa + (((qwn * 16 + (lane & 15)) * STRIDE + (lane >> 4) * 8) << 1);
    const unsigned aP = sPa + (((wm * 32 + (lane & 15)) * PSTRIDE + (lane >> 4) * 8) << 1);
    const unsigned bV = sVa + (((lane & 15) * STRIDE) << 1);

    const int srow = tid >> 3;          // softmax: 8 threads per row
    const int scol = (tid & 7) * 8;

    for (int kt = 0; kt < SS / BN; kt++) {
        __syncthreads();   // prev PV done before overwriting sK/sV; Q visible iter 0
        // ---- load K, V tiles ----
        const __half* Kt = Kg + (size_t)kt * BN * DD;
        const __half* Vt = Vg + (size_t)kt * BN * DD;
        #pragma unroll
        for (int i = tid; i < BN * 64; i += NTHREADS) {
            int r = i >> 6, c = i & 63;
            *(int4*)(sK + r * STRIDE + c * 8) = *(const int4*)(Kt + r * DD + c * 8);
            *(int4*)(sV + r * STRIDE + c * 8) = *(const int4*)(Vt + r * DD + c * 8);
        }
        __syncthreads();

        // ---- S = Q K^T (this warp: 16x16 tile at (qwm*16, qwn*16)) ----
        float sc[2][4];
        #pragma unroll
        for (int n = 0; n < 2; n++)
            #pragma unroll
            for (int d = 0; d < 4; d++) sc[n][d] = 0.f;
        #pragma unroll 4
        for (int k = 0; k < DD / 16; k++) {
            unsigned a0, a1, a2, a3, b0, b1, b2, b3;
            ldsm_x4(a0, a1, a2, a3, aQ + k * 32);
            ldsm_x4(b0, b1, b2, b3, bK + k * 32);
            mma16816(sc[0], a0, a1, a2, a3, b0, b2);
            mma16816(sc[1], a0, a1, a2, a3, b1, b3);
        }
        {
            int r0 = qwm * 16 + (lane >> 2);
            int c0 = qwn * 16 + (lane & 3) * 2;
            #pragma unroll
            for (int n = 0; n < 2; n++) {
                *(float2*)&sS[r0 * 64 + c0 + n * 8]       = make_float2(sc[n][0], sc[n][1]);
                *(float2*)&sS[(r0 + 8) * 64 + c0 + n * 8] = make_float2(sc[n][2], sc[n][3]);
            }
        }
        __syncthreads();

        // ---- online softmax (8 threads / row, row = srow) ----
        float p[8];
        {
            float vv[8];
            #pragma unroll
            for (int j = 0; j < 8; j++) vv[j] = sS[srow * 64 + scol + j];
            float mx = vv[0];
            #pragma unroll
            for (int j = 1; j < 8; j++) mx = fmaxf(mx, vv[j]);
            #pragma unroll
            for (int o = 1; o < 8; o <<= 1)
                mx = fmaxf(mx, __shfl_xor_sync(0xffffffffu, mx, o));
            float mold = sM[srow];
            float mnew = fmaxf(mold, mx);
            float s = 0.f;
            #pragma unroll
            for (int j = 0; j < 8; j++) { p[j] = __expf(vv[j] - mnew); s += p[j]; }
            #pragma unroll
            for (int o = 1; o < 8; o <<= 1)
                s += __shfl_xor_sync(0xffffffffu, s, o);
            if ((tid & 7) == 0) {
                float f = __expf(mold - mnew);
                sM[srow] = mnew;
                sL[srow] = sL[srow] * f + s;
                sF[srow] = f;
            }
        }
        __syncthreads();   // all sS reads done; stats visible

        // ---- write P (fp16, overlays sS) + rescale out accumulators ----
        {
            #pragma unroll
            for (int j = 0; j < 4; j++)
                *(__half2*)(sP + srow * PSTRIDE + scol + 2 * j) =
                    __floats2half2_rn(p[2 * j], p[2 * j + 1]);
            int rA = wm * 32 + (lane >> 2);
            float f0 = sF[rA], f1 = sF[rA + 8], f2 = sF[rA + 16], f3 = sF[rA + 24];
            #pragma unroll
            for (int n = 0; n < 8; n++) {
                acc[0][n][0] *= f0; acc[0][n][1] *= f0;
                acc[0][n][2] *= f1; acc[0][n][3] *= f1;
                acc[1][n][0] *= f2; acc[1][n][1] *= f2;
                acc[1][n][2] *= f3; acc[1][n][3] *= f3;
            }
        }
        __syncthreads();   // P visible

        // ---- out += P @ V (this warp: rows [wm*32,+32), cols [wn*64,+64)) ----
        #pragma unroll
        for (int ks = 0; ks < BN / 16; ks++) {
            unsigned a00, a01, a02, a03, a10, a11, a12, a13;
            ldsm_x4(a00, a01, a02, a03, aP + ks * 32);
            ldsm_x4(a10, a11, a12, a13, aP + 16 * PSTRIDE * 2 + ks * 32);
            #pragma unroll
            for (int n = 0; n < 8; n++) {
                unsigned b0, b1;
                ldsm_x2_trans(b0, b1,
                              bV + ks * 16 * STRIDE * 2 + (wn * 64 + n * 8) * 2);
                mma16816(acc[0][n], a00, a01, a02, a03, b0, b1);
                mma16816(acc[1][n], a10, a11, a12, a13, b0, b1);
            }
        }
    }
    __syncthreads();

    // ---- epilogue: out = acc / l ----
    {
        int rA = wm * 32 + (lane >> 2);
        float l0 = 1.f / sL[rA], l1 = 1.f / sL[rA + 8];
        float l2 = 1.f / sL[rA + 16], l3 = 1.f / sL[rA + 24];
        int c0 = wn * 64 + (lane & 3) * 2;
        float* ob = out + ((size_t)b * SS + q0) * DD;
        #pragma unroll
        for (int n = 0; n < 8; n++) {
            *(float2*)&ob[(size_t)(rA)*DD + c0 + n * 8] =
                make_float2(acc[0][n][0] * l0, acc[0][n][1] * l0);
            *(float2*)&ob[(size_t)(rA + 8) * DD + c0 + n * 8] =
                make_float2(acc[0][n][2] * l1, acc[0][n][3] * l1);
            *(float2*)&ob[(size_t)(rA + 16) * DD + c0 + n * 8] =
                make_float2(acc[1][n][0] * l2, acc[1][n][1] * l2);
            *(float2*)&ob[(size_t)(rA + 24) * DD + c0 + n * 8] =
                make_float2(acc[1][n][2] * l3, acc[1][n][3] * l3);
        }
    }
}

// ---------------------------------------------------------------------------
extern "C" void kernel_launch(void* const* d_in, const int* in_sizes, int n_in,
                              void* d_out, int out_size) {
    const float* v = (const float*)d_in[0];   // value
    const float* k = (const float*)d_in[1];   // key
    const float* q = (const float*)d_in[2];   // query
    float* out = (float*)d_out;

    convert_all_kernel<<<2048, 512>>>(v, k, q);

    cudaFuncSetAttribute(attn_kernel, cudaFuncAttributeMaxDynamicSharedMemorySize,
                         SMEM_BYTES);
    attn_kernel<<<dim3(SS / BM, BB), NTHREADS, SMEM_BYTES>>>(out);
}

// round 2
// speedup vs baseline: 1.0040x; 1.0040x over previous
#include <cuda_runtime.h>
#include <cuda_fp16.h>

// Problem: SelfAttention  B=8, S=2048, D=512, fp32 in/out.
// Inputs in metadata order: d_in[0]=value, d_in[1]=key, d_in[2]=query.
//
// Kernel 1: convert fp32 -> fp16 scratch (Q pre-scaled by 1/sqrt(D)).
// Kernel 2: fused flash attention, one CTA per (batch, 64-query tile),
//           512 threads, mma.sync m16n8k16 f32.f16 for QK^T and P@V,
//           online softmax, fp32 accumulators.

#define BB 8
#define SS 2048
#define DD 512
#define BM 64
#define BN 64
#define NTHREADS 512
#define STRIDE 520              // halves per smem tile row (pad: conflict-free LDSM)

// ---- smem layout (bytes) ----
#define OFF_K 66560             // 64*520*2
#define OFF_V 133120
#define OFF_S 199680
#define OFF_M 216064
#define OFF_L 216320
#define OFF_F 216576
#define SMEM_BYTES 216832
#define PSTRIDE 72              // halves per P row (overlaid on sS)

__device__ __half g_Qh[BB * SS * DD];
__device__ __half g_Kh[BB * SS * DD];
__device__ __half g_Vh[BB * SS * DD];

// ---------------------------------------------------------------------------
__global__ void convert_all_kernel(const float* __restrict__ v,
                                   const float* __restrict__ k,
                                   const float* __restrict__ q) {
    const float qscale = 0.044194173824159216f;  // 1/sqrt(512)
    const int n4 = BB * SS * DD / 4;
    for (int i = blockIdx.x * blockDim.x + threadIdx.x; i < n4;
         i += gridDim.x * blockDim.x) {
        float4 a = ((const float4*)q)[i];
        ((__half2*)g_Qh)[2 * i]     = __floats2half2_rn(a.x * qscale, a.y * qscale);
        ((__half2*)g_Qh)[2 * i + 1] = __floats2half2_rn(a.z * qscale, a.w * qscale);
        float4 bk = ((const float4*)k)[i];
        ((__half2*)g_Kh)[2 * i]     = __floats2half2_rn(bk.x, bk.y);
        ((__half2*)g_Kh)[2 * i + 1] = __floats2half2_rn(bk.z, bk.w);
        float4 c = ((const float4*)v)[i];
        ((__half2*)g_Vh)[2 * i]     = __floats2half2_rn(c.x, c.y);
        ((__half2*)g_Vh)[2 * i + 1] = __floats2half2_rn(c.z, c.w);
    }
}

// ---------------------------------------------------------------------------
__device__ __forceinline__ void ldsm_x4(unsigned& r0, unsigned& r1, unsigned& r2,
                                        unsigned& r3, unsigned addr) {
    asm volatile("ldmatrix.sync.aligned.m8n8.x4.shared.b16 {%0,%1,%2,%3}, [%4];"
                 : "=r"(r0), "=r"(r1), "=r"(r2), "=r"(r3)
                 : "r"(addr));
}
__device__ __forceinline__ void ldsm_x2_trans(unsigned& r0, unsigned& r1,
                                              unsigned addr) {
    asm volatile("ldmatrix.sync.aligned.m8n8.x2.trans.shared.b16 {%0,%1}, [%2];"
                 : "=r"(r0), "=r"(r1)
                 : "r"(addr));
}
__device__ __forceinline__ void mma16816(float* d, unsigned a0, unsigned a1,
                                         unsigned a2, unsigned a3, unsigned b0,
                                         unsigned b1) {
    asm volatile(
        "mma.sync.aligned.m16n8k16.row.col.f32.f16.f16.f32 "
        "{%0,%1,%2,%3}, {%4,%5,%6,%7}, {%8,%9}, {%0,%1,%2,%3};"
        : "+f"(d[0]), "+f"(d[1]), "+f"(d[2]), "+f"(d[3])
        : "r"(a0), "r"(a1), "r"(a2), "r"(a3), "r"(b0), "r"(b1));
}

// ---------------------------------------------------------------------------
__global__ void __launch_bounds__(NTHREADS, 1)
attn_kernel(float* __restrict__ out) {
    extern __shared__ char smem[];
    __half* sQ = (__half*)(smem);
    __half* sK = (__half*)(smem + OFF_K);
    __half* sV = (__half*)(smem + OFF_V);
    float*  sS = (float*)(smem + OFF_S);
    __half* sP = (__half*)(smem + OFF_S);   // overlaid; guarded by barriers
    float*  sM = (float*)(smem + OFF_M);
    float*  sL = (float*)(smem + OFF_L);
    float*  sF = (float*)(smem + OFF_F);

    const int tid  = threadIdx.x;
    const int warp = tid >> 5;
    const int lane = tid & 31;
    const int b    = blockIdx.y;
    const int q0   = blockIdx.x * BM;

    const __half* Qg = g_Qh + ((size_t)b * SS + q0) * DD;
    const __half* Kg = g_Kh + (size_t)b * SS * DD;
    const __half* Vg = g_Vh + (size_t)b * SS * DD;

    // ---- load Q tile (64 x 512 halves) ----
    #pragma unroll
    for (int i = tid; i < BM * 64; i += NTHREADS) {
        int r = i >> 6, c = i & 63;
        *(int4*)(sQ + r * STRIDE + c * 8) = *(const int4*)(Qg + r * DD + c * 8);
    }
    if (tid < BM) { sM[tid] = -1e30f; sL[tid] = 0.f; }

    // warp roles: QK 4x4 (16x16 S each); PV 2x8 (32 rows x 64 cols each)
    const int qwm = warp >> 2, qwn = warp & 3;
    const int wm  = warp >> 3, wn  = warp & 7;

    float acc[2][8][4];
    #pragma unroll
    for (int m = 0; m < 2; m++)
        #pragma unroll
        for (int n = 0; n < 8; n++)
            #pragma unroll
            for (int d = 0; d < 4; d++) acc[m][n][d] = 0.f;

    const unsigned sQa = (unsigned)__cvta_generic_to_shared(sQ);
    const unsigned sKa = (unsigned)__cvta_generic_to_shared(sK);
    const unsigned sVa = (unsigned)__cvta_generic_to_shared(sV);
    const unsigned sPa = (unsigned)__cvta_generic_to_shared(sP);

    const unsigned aQ = sQa + (((qwm * 16 + (lane & 15)) * STRIDE + (lane >> 4) * 8) << 1);
    const unsigned bK = sKa + (((qwn * 16 + (lane & 15)) * STRIDE + (lane >> 4) * 8) << 1);
    const unsigned aP = sPa + (((wm * 32 + (lane & 15)) * PSTRIDE + (lane >> 4) * 8) << 1);
    const unsigned bV = sVa + (((lane & 15) * STRIDE) << 1);

    const int srow = tid >> 3;          // softmax: 8 threads per row
    const int scol = (tid & 7) * 8;

    for (int kt = 0; kt < SS / BN; kt++) {
        __syncthreads();   // prev PV done before overwriting sK/sV; Q visible iter 0
        // ---- load K, V tiles ----
        const __half* Kt = Kg + (size_t)kt * BN * DD;
        const __half* Vt = Vg + (size_t)kt * BN * DD;
        #pragma unroll
        for (int i = tid; i < BN * 64; i += NTHREADS) {
            int r = i >> 6, c = i & 63;
            *(int4*)(sK + r * STRIDE + c * 8) = *(const int4*)(Kt + r * DD + c * 8);
            *(int4*)(sV + r * STRIDE + c * 8) = *(const int4*)(Vt + r * DD + c * 8);
        }
        __syncthreads();

        // ---- S = Q K^T (this warp: 16x16 tile at (qwm*16, qwn*16)) ----
        float sc[2][4];
        #pragma unroll
        for (int n = 0; n < 2; n++)
            #pragma unroll
            for (int d = 0; d < 4; d++) sc[n][d] = 0.f;
        #pragma unroll 4
        for (int k = 0; k < DD / 16; k++) {
            unsigned a0, a1, a2, a3, b0, b1, b2, b3;
            ldsm_x4(a0, a1, a2, a3, aQ + k * 32);
            ldsm_x4(b0, b1, b2, b3, bK + k * 32);
            mma16816(sc[0], a0, a1, a2, a3, b0, b2);
            mma16816(sc[1], a0, a1, a2, a3, b1, b3);
        }
        {
            int r0 = qwm * 16 + (lane >> 2);
            int c0 = qwn * 16 + (lane & 3) * 2;
            #pragma unroll
            for (int n = 0; n < 2; n++) {
                *(float2*)&sS[r0 * 64 + c0 + n * 8]       = make_float2(sc[n][0], sc[n][1]);
                *(float2*)&sS[(r0 + 8) * 64 + c0 + n * 8] = make_float2(sc[n][2], sc[n][3]);
            }
        }
        __syncthreads();

        // ---- online softmax (8 threads / row, row = srow) ----
        float p[8];
        {
            float vv[8];
            #pragma unroll
            for (int j = 0; j < 8; j++) vv[j] = sS[srow * 64 + scol + j];
            float mx = vv[0];
            #pragma unroll
            for (int j = 1; j < 8; j++) mx = fmaxf(mx, vv[j]);
            #pragma unroll
            for (int o = 1; o < 8; o <<= 1)
                mx = fmaxf(mx, __shfl_xor_sync(0xffffffffu, mx, o));
            float mold = sM[srow];
            float mnew = fmaxf(mold, mx);
            float s = 0.f;
            #pragma unroll
            for (int j = 0; j < 8; j++) { p[j] = __expf(vv[j] - mnew); s += p[j]; }
            #pragma unroll
            for (int o = 1; o < 8; o <<= 1)
                s += __shfl_xor_sync(0xffffffffu, s, o);
            if ((tid & 7) == 0) {
                float f = __expf(mold - mnew);
                sM[srow] = mnew;
                sL[srow] = sL[srow] * f + s;
                sF[srow] = f;
            }
        }
        __syncthreads();   // all sS reads done; stats visible

        // ---- write P (fp16, overlays sS) + rescale out accumulators ----
        {
            #pragma unroll
            for (int j = 0; j < 4; j++)
                *(__half2*)(sP + srow * PSTRIDE + scol + 2 * j) =
                    __floats2half2_rn(p[2 * j], p[2 * j + 1]);
            int rA = wm * 32 + (lane >> 2);
            float f0 = sF[rA], f1 = sF[rA + 8], f2 = sF[rA + 16], f3 = sF[rA + 24];
            #pragma unroll
            for (int n = 0; n < 8; n++) {
                acc[0][n][0] *= f0; acc[0][n][1] *= f0;
                acc[0][n][2] *= f1; acc[0][n][3] *= f1;
                acc[1][n][0] *= f2; acc[1][n][1] *= f2;
                acc[1][n][2] *= f3; acc[1][n][3] *= f3;
            }
        }
        __syncthreads();   // P visible

        // ---- out += P @ V (this warp: rows [wm*32,+32), cols [wn*64,+64)) ----
        #pragma unroll
        for (int ks = 0; ks < BN / 16; ks++) {
            unsigned a00, a01, a02, a03, a10, a11, a12, a13;
            ldsm_x4(a00, a01, a02, a03, aP + ks * 32);
            ldsm_x4(a10, a11, a12, a13, aP + 16 * PSTRIDE * 2 + ks * 32);
            #pragma unroll
            for (int n = 0; n < 8; n++) {
                unsigned b0, b1;
                ldsm_x2_trans(b0, b1,
                              bV + ks * 16 * STRIDE * 2 + (wn * 64 + n * 8) * 2);
                mma16816(acc[0][n], a00, a01, a02, a03, b0, b1);
                mma16816(acc[1][n], a10, a11, a12, a13, b0, b1);
            }
        }
    }
    __syncthreads();

    // ---- epilogue: out = acc / l ----
    {
        int rA = wm * 32 + (lane >> 2);
        float l0 = 1.f / sL[rA], l1 = 1.f / sL[rA + 8];
        float l2 = 1.f / sL[rA + 16], l3 = 1.f / sL[rA + 24];
        int c0 = wn * 64 + (lane & 3) * 2;
        float* ob = out + ((size_t)b * SS + q0) * DD;
        #pragma unroll
        for (int n = 0; n < 8; n++) {
            *(float2*)&ob[(size_t)(rA)*DD + c0 + n * 8] =
                make_float2(acc[0][n][0] * l0, acc[0][n][1] * l0);
            *(float2*)&ob[(size_t)(rA + 8) * DD + c0 + n * 8] =
                make_float2(acc[0][n][2] * l1, acc[0][n][3] * l1);
            *(float2*)&ob[(size_t)(rA + 16) * DD + c0 + n * 8] =
                make_float2(acc[1][n][0] * l2, acc[1][n][1] * l2);
            *(float2*)&ob[(size_t)(rA + 24) * DD + c0 + n * 8] =
                make_float2(acc[1][n][2] * l3, acc[1][n][3] * l3);
        }
    }
}

// ---------------------------------------------------------------------------
extern "C" void kernel_launch(void* const* d_in, const int* in_sizes, int n_in,
                              void* d_out, int out_size) {
    const float* v = (const float*)d_in[0];   // value
    const float* k = (const float*)d_in[1];   // key
    const float* q = (const float*)d_in[2];   // query
    float* out = (float*)d_out;

    convert_all_kernel<<<2048, 512>>>(v, k, q);

    cudaFuncSetAttribute(attn_kernel, cudaFuncAttributeMaxDynamicSharedMemorySize,
                         SMEM_BYTES);
    attn_kernel<<<dim3(SS / BM, BB), NTHREADS, SMEM_BYTES>>>(out);
}

// round 3
// speedup vs baseline: 1.0074x; 1.0034x over previous
#include <cuda_runtime.h>
#include <cuda_fp16.h>

// Problem: SelfAttention  B=8, S=2048, D=512, fp32 in/out.
// Inputs in metadata order: d_in[0]=value, d_in[1]=key, d_in[2]=query.
//
// Kernel 1: convert fp32 -> fp16 scratch (Q pre-scaled by 1/sqrt(D)).
// Kernel 2: fused flash attention, one CTA per (batch, 64-query tile),
//           512 threads, mma.sync m16n8k16 f32.f16 for QK^T and P@V,
//           online softmax, fp32 accumulators.

#define BB 8
#define SS 2048
#define DD 512
#define BM 64
#define BN 64
#define NTHREADS 512
#define STRIDE 520              // halves per smem tile row (pad: conflict-free LDSM)

// ---- smem layout (bytes) ----
#define OFF_K 66560             // 64*520*2
#define OFF_V 133120
#define OFF_S 199680
#define OFF_M 216064
#define OFF_L 216320
#define OFF_F 216576
#define SMEM_BYTES 216832
#define PSTRIDE 72              // halves per P row (overlaid on sS)

__device__ __half g_Qh[BB * SS * DD];
__device__ __half g_Kh[BB * SS * DD];
__device__ __half g_Vh[BB * SS * DD];

// ---------------------------------------------------------------------------
__global__ void convert_all_kernel(const float* __restrict__ v,
                                   const float* __restrict__ k,
                                   const float* __restrict__ q) {
    const float qscale = 0.044194173824159216f;  // 1/sqrt(512)
    const int n4 = BB * SS * DD / 4;
    for (int i = blockIdx.x * blockDim.x + threadIdx.x; i < n4;
         i += gridDim.x * blockDim.x) {
        float4 a = ((const float4*)q)[i];
        ((__half2*)g_Qh)[2 * i]     = __floats2half2_rn(a.x * qscale, a.y * qscale);
        ((__half2*)g_Qh)[2 * i + 1] = __floats2half2_rn(a.z * qscale, a.w * qscale);
        float4 bk = ((const float4*)k)[i];
        ((__half2*)g_Kh)[2 * i]     = __floats2half2_rn(bk.x, bk.y);
        ((__half2*)g_Kh)[2 * i + 1] = __floats2half2_rn(bk.z, bk.w);
        float4 c = ((const float4*)v)[i];
        ((__half2*)g_Vh)[2 * i]     = __floats2half2_rn(c.x, c.y);
        ((__half2*)g_Vh)[2 * i + 1] = __floats2half2_rn(c.z, c.w);
    }
}

// ---------------------------------------------------------------------------
__device__ __forceinline__ void ldsm_x4(unsigned& r0, unsigned& r1, unsigned& r2,
                                        unsigned& r3, unsigned addr) {
    asm volatile("ldmatrix.sync.aligned.m8n8.x4.shared.b16 {%0,%1,%2,%3}, [%4];"
                 : "=r"(r0), "=r"(r1), "=r"(r2), "=r"(r3)
                 : "r"(addr));
}
__device__ __forceinline__ void ldsm_x2_trans(unsigned& r0, unsigned& r1,
                                              unsigned addr) {
    asm volatile("ldmatrix.sync.aligned.m8n8.x2.trans.shared.b16 {%0,%1}, [%2];"
                 : "=r"(r0), "=r"(r1)
                 : "r"(addr));
}
__device__ __forceinline__ void mma16816(float* d, unsigned a0, unsigned a1,
                                         unsigned a2, unsigned a3, unsigned b0,
                                         unsigned b1) {
    asm volatile(
        "mma.sync.aligned.m16n8k16.row.col.f32.f16.f16.f32 "
        "{%0,%1,%2,%3}, {%4,%5,%6,%7}, {%8,%9}, {%0,%1,%2,%3};"
        : "+f"(d[0]), "+f"(d[1]), "+f"(d[2]), "+f"(d[3])
        : "r"(a0), "r"(a1), "r"(a2), "r"(a3), "r"(b0), "r"(b1));
}

// ---------------------------------------------------------------------------
__global__ void __launch_bounds__(NTHREADS, 1)
attn_kernel(float* __restrict__ out) {
    extern __shared__ char smem[];
    __half* sQ = (__half*)(smem);
    __half* sK = (__half*)(smem + OFF_K);
    __half* sV = (__half*)(smem + OFF_V);
    float*  sS = (float*)(smem + OFF_S);
    __half* sP = (__half*)(smem + OFF_S);   // overlaid; guarded by barriers
    float*  sM = (float*)(smem + OFF_M);
    float*  sL = (float*)(smem + OFF_L);
    float*  sF = (float*)(smem + OFF_F);

    const int tid  = threadIdx.x;
    const int warp = tid >> 5;
    const int lane = tid & 31;
    const int b    = blockIdx.y;
    const int q0   = blockIdx.x * BM;

    const __half* Qg = g_Qh + ((size_t)b * SS + q0) * DD;
    const __half* Kg = g_Kh + (size_t)b * SS * DD;
    const __half* Vg = g_Vh + (size_t)b * SS * DD;

    // ---- load Q tile (64 x 512 halves) ----
    #pragma unroll
    for (int i = tid; i < BM * 64; i += NTHREADS) {
        int r = i >> 6, c = i & 63;
        *(int4*)(sQ + r * STRIDE + c * 8) = *(const int4*)(Qg + r * DD + c * 8);
    }
    if (tid < BM) { sM[tid] = -1e30f; sL[tid] = 0.f; }

    // warp roles: QK 4x4 (16x16 S each); PV 2x8 (32 rows x 64 cols each)
    const int qwm = warp >> 2, qwn = warp & 3;
    const int wm  = warp >> 3, wn  = warp & 7;

    float acc[2][8][4];
    #pragma unroll
    for (int m = 0; m < 2; m++)
        #pragma unroll
        for (int n = 0; n < 8; n++)
            #pragma unroll
            for (int d = 0; d < 4; d++) acc[m][n][d] = 0.f;

    const unsigned sQa = (unsigned)__cvta_generic_to_shared(sQ);
    const unsigned sKa = (unsigned)__cvta_generic_to_shared(sK);
    const unsigned sVa = (unsigned)__cvta_generic_to_shared(sV);
    const unsigned sPa = (unsigned)__cvta_generic_to_shared(sP);

    const unsigned aQ = sQa + (((qwm * 16 + (lane & 15)) * STRIDE + (lane >> 4) * 8) << 1);
    const unsigned bK = sKa + (((qwn * 16 + (lane & 15)) * STRIDE + (lane >> 4) * 8) << 1);
    const unsigned aP = sPa + (((wm * 32 + (lane & 15)) * PSTRIDE + (lane >> 4) * 8) << 1);
    const unsigned bV = sVa + (((lane & 15) * STRIDE) << 1);

    const int srow = tid >> 3;          // softmax: 8 threads per row
    const int scol = (tid & 7) * 8;

    for (int kt = 0; kt < SS / BN; kt++) {
        __syncthreads();   // prev PV done before overwriting sK/sV; Q visible iter 0
        // ---- load K, V tiles ----
        const __half* Kt = Kg + (size_t)kt * BN * DD;
        const __half* Vt = Vg + (size_t)kt * BN * DD;
        #pragma unroll
        for (int i = tid; i < BN * 64; i += NTHREADS) {
            int r = i >> 6, c = i & 63;
            *(int4*)(sK + r * STRIDE + c * 8) = *(const int4*)(Kt + r * DD + c * 8);
            *(int4*)(sV + r * STRIDE + c * 8) = *(const int4*)(Vt + r * DD + c * 8);
        }
        __syncthreads();

        // ---- S = Q K^T (this warp: 16x16 tile at (qwm*16, qwn*16)) ----
        float sc[2][4];
        #pragma unroll
        for (int n = 0; n < 2; n++)
            #pragma unroll
            for (int d = 0; d < 4; d++) sc[n][d] = 0.f;
        #pragma unroll 4
        for (int k = 0; k < DD / 16; k++) {
            unsigned a0, a1, a2, a3, b0, b1, b2, b3;
            ldsm_x4(a0, a1, a2, a3, aQ + k * 32);
            ldsm_x4(b0, b1, b2, b3, bK + k * 32);
            mma16816(sc[0], a0, a1, a2, a3, b0, b2);
            mma16816(sc[1], a0, a1, a2, a3, b1, b3);
        }
        {
            int r0 = qwm * 16 + (lane >> 2);
            int c0 = qwn * 16 + (lane & 3) * 2;
            #pragma unroll
            for (int n = 0; n < 2; n++) {
                *(float2*)&sS[r0 * 64 + c0 + n * 8]       = make_float2(sc[n][0], sc[n][1]);
                *(float2*)&sS[(r0 + 8) * 64 + c0 + n * 8] = make_float2(sc[n][2], sc[n][3]);
            }
        }
        __syncthreads();

        // ---- online softmax (8 threads / row, row = srow) ----
        float p[8];
        {
            float vv[8];
            #pragma unroll
            for (int j = 0; j < 8; j++) vv[j] = sS[srow * 64 + scol + j];
            float mx = vv[0];
            #pragma unroll
            for (int j = 1; j < 8; j++) mx = fmaxf(mx, vv[j]);
            #pragma unroll
            for (int o = 1; o < 8; o <<= 1)
                mx = fmaxf(mx, __shfl_xor_sync(0xffffffffu, mx, o));
            float mold = sM[srow];
            float mnew = fmaxf(mold, mx);
            float s = 0.f;
            #pragma unroll
            for (int j = 0; j < 8; j++) { p[j] = __expf(vv[j] - mnew); s += p[j]; }
            #pragma unroll
            for (int o = 1; o < 8; o <<= 1)
                s += __shfl_xor_sync(0xffffffffu, s, o);
            if ((tid & 7) == 0) {
                float f = __expf(mold - mnew);
                sM[srow] = mnew;
                sL[srow] = sL[srow] * f + s;
                sF[srow] = f;
            }
        }
        __syncthreads();   // all sS reads done; stats visible

        // ---- write P (fp16, overlays sS) + rescale out accumulators ----
        {
            #pragma unroll
            for (int j = 0; j < 4; j++)
                *(__half2*)(sP + srow * PSTRIDE + scol + 2 * j) =
                    __floats2half2_rn(p[2 * j], p[2 * j + 1]);
            int rA = wm * 32 + (lane >> 2);
            float f0 = sF[rA], f1 = sF[rA + 8], f2 = sF[rA + 16], f3 = sF[rA + 24];
            #pragma unroll
            for (int n = 0; n < 8; n++) {
                acc[0][n][0] *= f0; acc[0][n][1] *= f0;
                acc[0][n][2] *= f1; acc[0][n][3] *= f1;
                acc[1][n][0] *= f2; acc[1][n][1] *= f2;
                acc[1][n][2] *= f3; acc[1][n][3] *= f3;
            }
        }
        __syncthreads();   // P visible

        // ---- out += P @ V (this warp: rows [wm*32,+32), cols [wn*64,+64)) ----
        #pragma unroll
        for (int ks = 0; ks < BN / 16; ks++) {
            unsigned a00, a01, a02, a03, a10, a11, a12, a13;
            ldsm_x4(a00, a01, a02, a03, aP + ks * 32);
            ldsm_x4(a10, a11, a12, a13, aP + 16 * PSTRIDE * 2 + ks * 32);
            #pragma unroll
            for (int n = 0; n < 8; n++) {
                unsigned b0, b1;
                ldsm_x2_trans(b0, b1,
                              bV + ks * 16 * STRIDE * 2 + (wn * 64 + n * 8) * 2);
                mma16816(acc[0][n], a00, a01, a02, a03, b0, b1);
                mma16816(acc[1][n], a10, a11, a12, a13, b0, b1);
            }
        }
    }
    __syncthreads();

    // ---- epilogue: out = acc / l ----
    {
        int rA = wm * 32 + (lane >> 2);
        float l0 = 1.f / sL[rA], l1 = 1.f / sL[rA + 8];
        float l2 = 1.f / sL[rA + 16], l3 = 1.f / sL[rA + 24];
        int c0 = wn * 64 + (lane & 3) * 2;
        float* ob = out + ((size_t)b * SS + q0) * DD;
        #pragma unroll
        for (int n = 0; n < 8; n++) {
            *(float2*)&ob[(size_t)(rA)*DD + c0 + n * 8] =
                make_float2(acc[0][n][0] * l0, acc[0][n][1] * l0);
            *(float2*)&ob[(size_t)(rA + 8) * DD + c0 + n * 8] =
                make_float2(acc[0][n][2] * l1, acc[0][n][3] * l1);
            *(float2*)&ob[(size_t)(rA + 16) * DD + c0 + n * 8] =
                make_float2(acc[1][n][0] * l2, acc[1][n][1] * l2);
            *(float2*)&ob[(size_t)(rA + 24) * DD + c0 + n * 8] =
                make_float2(acc[1][n][2] * l3, acc[1][n][3] * l3);
        }
    }
}

// ---------------------------------------------------------------------------
extern "C" void kernel_launch(void* const* d_in, const int* in_sizes, int n_in,
                              void* d_out, int out_size) {
    const float* v = (const float*)d_in[0];   // value
    const float* k = (const float*)d_in[1];   // key
    const float* q = (const float*)d_in[2];   // query
    float* out = (float*)d_out;

    convert_all_kernel<<<2048, 512>>>(v, k, q);

    cudaFuncSetAttribute(attn_kernel, cudaFuncAttributeMaxDynamicSharedMemorySize,
                         SMEM_BYTES);
    attn_kernel<<<dim3(SS / BM, BB), NTHREADS, SMEM_BYTES>>>(out);
}